// round 6
// baseline (speedup 1.0000x reference)
#include <cuda_runtime.h>

// Problem constants
#define Bn   2
#define Ln   2048
#define Dn   768
#define Hn   12
#define DKn  64
#define D3   (3 * Dn)          // 2304
#define Mrows (Bn * Ln)        // 4096

// ---------------------------------------------------------------------------
// Scratch (device globals: no allocations allowed in kernel_launch)
// ---------------------------------------------------------------------------
__device__ float g_qkv[(size_t)Mrows * D3];             // 4096 x 2304  (37.7 MB)
__device__ float g_scores[(size_t)Bn * Hn * Ln * Ln];   // 24 x 2048 x 2048 (402 MB)
__device__ float g_y[(size_t)Mrows * Dn];               // 4096 x 768   (12.6 MB)

// ---------------------------------------------------------------------------
// Kernel 1/5: C[M,N] = A[M,K] @ B[K,N] + bias[N]
// 128x128 block tile, BK=8, 256 threads, 8x8 per thread (split-64 layout).
// Requires M%128==0, N%128==0, K%8==0. lda=K, ldb=N, ldc=N.
// ---------------------------------------------------------------------------
__global__ __launch_bounds__(256, 2) void sgemm_bias_kernel(
    const float* __restrict__ A, const float* __restrict__ B,
    const float* __restrict__ bias, float* __restrict__ C,
    int M, int N, int K)
{
    __shared__ float As[8][132];   // [k][m], padded row (132*4B = 16B-aligned rows)
    __shared__ float Bs[8][132];   // [k][n]

    const int tid = threadIdx.x;
    const int tx  = tid & 15;      // 0..15 -> n groups
    const int ty  = tid >> 4;      // 0..15 -> m groups
    const int m0  = blockIdx.y * 128;
    const int n0  = blockIdx.x * 128;

    const int arow = tid >> 1;             // 0..127
    const int ac4  = (tid & 1) * 4;        // 0 or 4
    const int brow = tid >> 5;             // 0..7
    const int bc4  = (tid & 31) * 4;       // 0..124

    const float* Ag = A + (size_t)(m0 + arow) * K + ac4;
    const float* Bg = B + (size_t)brow * N + n0 + bc4;

    float acc[8][8];
#pragma unroll
    for (int i = 0; i < 8; i++)
#pragma unroll
        for (int j = 0; j < 8; j++) acc[i][j] = 0.f;

    for (int kt = 0; kt < K; kt += 8) {
        float4 av = *(const float4*)(Ag + kt);
        float4 bv = *(const float4*)(Bg + (size_t)kt * N);
        As[ac4 + 0][arow] = av.x;
        As[ac4 + 1][arow] = av.y;
        As[ac4 + 2][arow] = av.z;
        As[ac4 + 3][arow] = av.w;
        *(float4*)&Bs[brow][bc4] = bv;
        __syncthreads();
#pragma unroll
        for (int k = 0; k < 8; k++) {
            float a[8], b[8];
            float4 t;
            t = *(const float4*)&As[k][ty * 4];      a[0]=t.x; a[1]=t.y; a[2]=t.z; a[3]=t.w;
            t = *(const float4*)&As[k][64 + ty * 4]; a[4]=t.x; a[5]=t.y; a[6]=t.z; a[7]=t.w;
            t = *(const float4*)&Bs[k][tx * 4];      b[0]=t.x; b[1]=t.y; b[2]=t.z; b[3]=t.w;
            t = *(const float4*)&Bs[k][64 + tx * 4]; b[4]=t.x; b[5]=t.y; b[6]=t.z; b[7]=t.w;
#pragma unroll
            for (int i = 0; i < 8; i++)
#pragma unroll
                for (int j = 0; j < 8; j++) acc[i][j] += a[i] * b[j];
        }
        __syncthreads();
    }

    float bb[8];
#pragma unroll
    for (int j = 0; j < 8; j++) {
        int n = n0 + ((j < 4) ? (tx * 4 + j) : (64 + tx * 4 + j - 4));
        bb[j] = bias[n];
    }
#pragma unroll
    for (int i = 0; i < 8; i++) {
        int m = m0 + ((i < 4) ? (ty * 4 + i) : (64 + ty * 4 + i - 4));
        float* Crow = C + (size_t)m * N + n0;
        float4 r0, r1;
        r0.x = acc[i][0] + bb[0]; r0.y = acc[i][1] + bb[1];
        r0.z = acc[i][2] + bb[2]; r0.w = acc[i][3] + bb[3];
        r1.x = acc[i][4] + bb[4]; r1.y = acc[i][5] + bb[5];
        r1.z = acc[i][6] + bb[6]; r1.w = acc[i][7] + bb[7];
        *(float4*)&Crow[tx * 4]      = r0;
        *(float4*)&Crow[64 + tx * 4] = r1;
    }
}

// ---------------------------------------------------------------------------
// Kernel 2: scores = (Q @ K^T) * (1/sqrt(64)), per (b,h). Causal block skip.
// grid: (k_tile=16, q_tile=16, b*h=24). Blocks with bx > by do nothing.
// ---------------------------------------------------------------------------
__global__ __launch_bounds__(256, 2) void scores_kernel()
{
    const int bx = blockIdx.x, by = blockIdx.y;
    if (bx > by) return;                 // fully above diagonal -> never read
    const int bh = blockIdx.z;
    const int b  = bh / Hn, h = bh % Hn;

    const float* Q  = g_qkv + (size_t)b * Ln * D3 + h * DKn;
    const float* Kp = g_qkv + (size_t)b * Ln * D3 + Dn + h * DKn;
    float*       C  = g_scores + (size_t)bh * Ln * Ln;

    __shared__ float As[8][132];   // [k][q]
    __shared__ float Bs[8][132];   // [k][kv]

    const int tid = threadIdx.x;
    const int tx  = tid & 15;
    const int ty  = tid >> 4;
    const int m0  = by * 128;
    const int n0  = bx * 128;

    const int row = tid >> 1;             // 0..127
    const int c4  = (tid & 1) * 4;        // 0 or 4

    const float* Qg = Q  + (size_t)(m0 + row) * D3 + c4;
    const float* Kg = Kp + (size_t)(n0 + row) * D3 + c4;

    float acc[8][8];
#pragma unroll
    for (int i = 0; i < 8; i++)
#pragma unroll
        for (int j = 0; j < 8; j++) acc[i][j] = 0.f;

    for (int kt = 0; kt < DKn; kt += 8) {
        float4 av = *(const float4*)(Qg + kt);
        float4 bv = *(const float4*)(Kg + kt);
        As[c4 + 0][row] = av.x; As[c4 + 1][row] = av.y;
        As[c4 + 2][row] = av.z; As[c4 + 3][row] = av.w;
        Bs[c4 + 0][row] = bv.x; Bs[c4 + 1][row] = bv.y;
        Bs[c4 + 2][row] = bv.z; Bs[c4 + 3][row] = bv.w;
        __syncthreads();
#pragma unroll
        for (int k = 0; k < 8; k++) {
            float a[8], bb[8];
            float4 t;
            t = *(const float4*)&As[k][ty * 4];      a[0]=t.x; a[1]=t.y; a[2]=t.z; a[3]=t.w;
            t = *(const float4*)&As[k][64 + ty * 4]; a[4]=t.x; a[5]=t.y; a[6]=t.z; a[7]=t.w;
            t = *(const float4*)&Bs[k][tx * 4];      bb[0]=t.x; bb[1]=t.y; bb[2]=t.z; bb[3]=t.w;
            t = *(const float4*)&Bs[k][64 + tx * 4]; bb[4]=t.x; bb[5]=t.y; bb[6]=t.z; bb[7]=t.w;
#pragma unroll
            for (int i = 0; i < 8; i++)
#pragma unroll
                for (int j = 0; j < 8; j++) acc[i][j] += a[i] * bb[j];
        }
        __syncthreads();
    }

    const float scale = 0.125f;          // 1/sqrt(64)
#pragma unroll
    for (int i = 0; i < 8; i++) {
        int m = m0 + ((i < 4) ? (ty * 4 + i) : (64 + ty * 4 + i - 4));
        float* Crow = C + (size_t)m * Ln + n0;
        float4 r0, r1;
        r0.x = acc[i][0] * scale; r0.y = acc[i][1] * scale;
        r0.z = acc[i][2] * scale; r0.w = acc[i][3] * scale;
        r1.x = acc[i][4] * scale; r1.y = acc[i][5] * scale;
        r1.z = acc[i][6] * scale; r1.w = acc[i][7] * scale;
        *(float4*)&Crow[tx * 4]      = r0;
        *(float4*)&Crow[64 + tx * 4] = r1;
    }
}

// ---------------------------------------------------------------------------
// Kernel 3: causal softmax over row q (valid length q+1), in place.
// Zero-pads (q, round_up_128(q+1)) so the PV GEMM can read full 128-tiles.
// grid: (L, B*H), 256 threads.
// ---------------------------------------------------------------------------
__global__ __launch_bounds__(256) void softmax_kernel()
{
    const int q  = blockIdx.x;
    const int bh = blockIdx.y;
    float* row = g_scores + ((size_t)bh * Ln + q) * Ln;
    const int n = q + 1;
    const int tid  = threadIdx.x;
    const int lane = tid & 31;
    const int warp = tid >> 5;

    __shared__ float sred[8];
    __shared__ float sbc;

    float v[8];
    float mx = -3.4e38f;
#pragma unroll
    for (int j = 0; j < 8; j++) {
        int idx = tid + j * 256;
        v[j] = (idx < n) ? row[idx] : -3.4e38f;
        mx = fmaxf(mx, v[j]);
    }
#pragma unroll
    for (int off = 16; off > 0; off >>= 1)
        mx = fmaxf(mx, __shfl_xor_sync(0xFFFFFFFFu, mx, off));
    if (lane == 0) sred[warp] = mx;
    __syncthreads();
    if (tid == 0) {
        float m = sred[0];
#pragma unroll
        for (int w = 1; w < 8; w++) m = fmaxf(m, sred[w]);
        sbc = m;
    }
    __syncthreads();
    mx = sbc;

    float s = 0.f;
#pragma unroll
    for (int j = 0; j < 8; j++) {
        int idx = tid + j * 256;
        if (idx < n) { v[j] = __expf(v[j] - mx); s += v[j]; }
        else          v[j] = 0.f;
    }
#pragma unroll
    for (int off = 16; off > 0; off >>= 1)
        s += __shfl_xor_sync(0xFFFFFFFFu, s, off);
    __syncthreads();               // protect sred reuse
    if (lane == 0) sred[warp] = s;
    __syncthreads();
    if (tid == 0) {
        float t = 0.f;
#pragma unroll
        for (int w = 0; w < 8; w++) t += sred[w];
        sbc = 1.f / t;
    }
    __syncthreads();
    const float inv = sbc;

#pragma unroll
    for (int j = 0; j < 8; j++) {
        int idx = tid + j * 256;
        if (idx < n) row[idx] = v[j] * inv;
    }
    // Zero padding so PV can read full 128-wide k-tiles for this q-block.
    const int pad_end = ((q >> 7) + 1) << 7;
    for (int idx = n + tid; idx < pad_end; idx += 256) row[idx] = 0.f;
}

// ---------------------------------------------------------------------------
// Kernel 4: O = P @ V, per (b,h). M=2048, N=64, K bounded causally per q-tile.
// 128x64 block tile, BK=8, 256 threads, 8x4 per thread.
// grid: (1, q_tile=16, 24).
// ---------------------------------------------------------------------------
__global__ __launch_bounds__(256, 2) void pv_kernel()
{
    const int by = blockIdx.y;
    const int bh = blockIdx.z;
    const int b  = bh / Hn, h = bh % Hn;

    const float* P = g_scores + (size_t)bh * Ln * Ln;
    const float* V = g_qkv + (size_t)b * Ln * D3 + 2 * Dn + h * DKn;
    float*       O = g_y + (size_t)b * Ln * Dn + h * DKn;

    __shared__ float As[8][132];   // [k][q]
    __shared__ float Bs[8][68];    // [k][d]   (68*4B rows keep 16B alignment)

    const int tid = threadIdx.x;
    const int tx  = tid & 15;      // d group (4 cols each)
    const int ty  = tid >> 4;      // q group (split-64, 8 rows each)
    const int m0  = by * 128;

    const int prow = tid >> 1;
    const int pc4  = (tid & 1) * 4;
    const int vrow = tid >> 5;             // 0..7
    const int vc2  = (tid & 31) * 2;       // 0..62

    float acc[8][4];
#pragma unroll
    for (int i = 0; i < 8; i++)
#pragma unroll
        for (int j = 0; j < 4; j++) acc[i][j] = 0.f;

    const int nkt = (by + 1) * 128;        // causal bound (padded with zeros)
    for (int kt = 0; kt < nkt; kt += 8) {
        float4 pv = *(const float4*)&P[(size_t)(m0 + prow) * Ln + kt + pc4];
        float2 vv = *(const float2*)&V[(size_t)(kt + vrow) * D3 + vc2];
        As[pc4 + 0][prow] = pv.x; As[pc4 + 1][prow] = pv.y;
        As[pc4 + 2][prow] = pv.z; As[pc4 + 3][prow] = pv.w;
        Bs[vrow][vc2]     = vv.x;
        Bs[vrow][vc2 + 1] = vv.y;
        __syncthreads();
#pragma unroll
        for (int k = 0; k < 8; k++) {
            float a[8];
            float4 t;
            t = *(const float4*)&As[k][ty * 4];      a[0]=t.x; a[1]=t.y; a[2]=t.z; a[3]=t.w;
            t = *(const float4*)&As[k][64 + ty * 4]; a[4]=t.x; a[5]=t.y; a[6]=t.z; a[7]=t.w;
            float4 bb = *(const float4*)&Bs[k][tx * 4];
#pragma unroll
            for (int i = 0; i < 8; i++) {
                acc[i][0] += a[i] * bb.x;
                acc[i][1] += a[i] * bb.y;
                acc[i][2] += a[i] * bb.z;
                acc[i][3] += a[i] * bb.w;
            }
        }
        __syncthreads();
    }

#pragma unroll
    for (int i = 0; i < 8; i++) {
        int m = m0 + ((i < 4) ? (ty * 4 + i) : (64 + ty * 4 + i - 4));
        float4 r;
        r.x = acc[i][0]; r.y = acc[i][1]; r.z = acc[i][2]; r.w = acc[i][3];
        *(float4*)&O[(size_t)m * Dn + tx * 4] = r;
    }
}

// ---------------------------------------------------------------------------
// Launch
// ---------------------------------------------------------------------------
extern "C" void kernel_launch(void* const* d_in, const int* in_sizes, int n_in,
                              void* d_out, int out_size)
{
    (void)in_sizes; (void)n_in; (void)out_size;
    const float* x    = (const float*)d_in[0];
    // d_in[1] = mask (causal -1e9 additive) — implemented structurally, unused.
    const float* Wqkv = (const float*)d_in[2];
    const float* bqkv = (const float*)d_in[3];
    const float* Wo   = (const float*)d_in[4];
    const float* bo   = (const float*)d_in[5];
    float* out = (float*)d_out;

    float *p_qkv = nullptr, *p_y = nullptr;
    cudaGetSymbolAddress((void**)&p_qkv, g_qkv);
    cudaGetSymbolAddress((void**)&p_y, g_y);

    // 1) QKV projection: (4096 x 768) @ (768 x 2304) + bqkv
    sgemm_bias_kernel<<<dim3(D3 / 128, Mrows / 128), 256>>>(
        x, Wqkv, bqkv, p_qkv, Mrows, D3, Dn);

    // 2) Scores: Q K^T / sqrt(dk), causal block-skipped
    scores_kernel<<<dim3(Ln / 128, Ln / 128, Bn * Hn), 256>>>();

    // 3) Causal softmax with zero padding
    softmax_kernel<<<dim3(Ln, Bn * Hn), 256>>>();

    // 4) PV: O = P @ V
    pv_kernel<<<dim3(1, Ln / 128, Bn * Hn), 256>>>();

    // 5) Output projection: (4096 x 768) @ (768 x 768) + bo
    sgemm_bias_kernel<<<dim3(Dn / 128, Mrows / 128), 256>>>(
        p_y, Wo, bo, out, Mrows, Dn, Dn);
}

// round 9
// speedup vs baseline: 1.6464x; 1.6464x over previous
#include <cuda_runtime.h>
#include <cstdint>

// Problem constants
#define Bn   2
#define Ln   2048
#define Dn   768
#define Hn   12
#define DKn  64
#define D3   (3 * Dn)          // 2304
#define Mrows (Bn * Ln)        // 4096

// ---------------------------------------------------------------------------
// Scratch (device globals: no allocations allowed in kernel_launch)
// ---------------------------------------------------------------------------
__device__ float g_qkv[(size_t)Mrows * D3];             // 4096 x 2304
__device__ float g_scores[(size_t)Bn * Hn * Ln * Ln];   // 24 x 2048 x 2048
__device__ float g_y[(size_t)Mrows * Dn];               // 4096 x 768

// ---------------------------------------------------------------------------
// tf32 helpers
// ---------------------------------------------------------------------------
__device__ __forceinline__ uint32_t f2tf32(float x) {
    uint32_t r;
    asm("cvt.rna.tf32.f32 %0, %1;" : "=r"(r) : "f"(x));
    return r;
}

// D(16x8) += A(16x8,row) * B(8x8,col), tf32 in, fp32 accum
__device__ __forceinline__ void mma8(float* c,
                                     uint32_t a0, uint32_t a1, uint32_t a2, uint32_t a3,
                                     uint32_t b0, uint32_t b1) {
    asm volatile(
        "mma.sync.aligned.m16n8k8.row.col.f32.tf32.tf32.f32 "
        "{%0,%1,%2,%3},{%4,%5,%6,%7},{%8,%9},{%0,%1,%2,%3};"
        : "+f"(c[0]), "+f"(c[1]), "+f"(c[2]), "+f"(c[3])
        : "r"(a0), "r"(a1), "r"(a2), "r"(a3), "r"(b0), "r"(b1));
}

// ---------------------------------------------------------------------------
// Kernel 1/5: C[M,N] = A[M,K] @ B[K,N] + bias[N]   (tf32 tensor core)
// 128x128 block, BK=8, 256 threads = 8 warps (2m x 4n), each warp 64x32.
// Requires M%128==0, N%128==0, K%8==0.
// ---------------------------------------------------------------------------
__global__ __launch_bounds__(256, 2) void sgemm_bias_tc(
    const float* __restrict__ A, const float* __restrict__ B,
    const float* __restrict__ bias, float* __restrict__ C,
    int M, int N, int K)
{
    // stride 136: 136 % 32 == 8  ->  frag loads (tig*8 + g) hit all 32 banks
    __shared__ uint32_t As[8][136];   // [k][m]
    __shared__ uint32_t Bs[8][136];   // [k][n]

    const int tid  = threadIdx.x;
    const int lane = tid & 31;
    const int wid  = tid >> 5;
    const int g    = lane >> 2;       // 0..7
    const int tig  = lane & 3;        // 0..3
    const int wm0  = (wid >> 2) * 64; // warp m offset (0/64)
    const int wn0  = (wid & 3) * 32;  // warp n offset (0/32/64/96)
    const int m0   = blockIdx.y * 128;
    const int n0   = blockIdx.x * 128;

    const int arow = tid >> 1;            // 0..127
    const int ac4  = (tid & 1) * 4;       // 0 or 4
    const int brow = tid >> 5;            // 0..7
    const int bc4  = (tid & 31) * 4;      // 0..124

    const float* Ag = A + (size_t)(m0 + arow) * K + ac4;
    const float* Bg = B + (size_t)brow * N + n0 + bc4;

    float acc[4][4][4];
#pragma unroll
    for (int i = 0; i < 4; i++)
#pragma unroll
        for (int j = 0; j < 4; j++)
#pragma unroll
            for (int r = 0; r < 4; r++) acc[i][j][r] = 0.f;

    float4 av = *(const float4*)(Ag);
    float4 bv = *(const float4*)(Bg);

    for (int kt = 0; kt < K; kt += 8) {
        As[ac4 + 0][arow] = f2tf32(av.x);
        As[ac4 + 1][arow] = f2tf32(av.y);
        As[ac4 + 2][arow] = f2tf32(av.z);
        As[ac4 + 3][arow] = f2tf32(av.w);
        {
            uint4 p;
            p.x = f2tf32(bv.x); p.y = f2tf32(bv.y);
            p.z = f2tf32(bv.z); p.w = f2tf32(bv.w);
            *(uint4*)&Bs[brow][bc4] = p;
        }
        __syncthreads();

        if (kt + 8 < K) {                      // prefetch next tile
            av = *(const float4*)(Ag + kt + 8);
            bv = *(const float4*)(Bg + (size_t)(kt + 8) * N);
        }

        uint32_t b0[4], b1[4];
#pragma unroll
        for (int sn = 0; sn < 4; sn++) {
            b0[sn] = Bs[tig][wn0 + sn * 8 + g];
            b1[sn] = Bs[tig + 4][wn0 + sn * 8 + g];
        }
#pragma unroll
        for (int sm = 0; sm < 4; sm++) {
            const int mb = wm0 + sm * 16;
            uint32_t a0 = As[tig][mb + g];
            uint32_t a1 = As[tig][mb + 8 + g];
            uint32_t a2 = As[tig + 4][mb + g];
            uint32_t a3 = As[tig + 4][mb + 8 + g];
#pragma unroll
            for (int sn = 0; sn < 4; sn++)
                mma8(acc[sm][sn], a0, a1, a2, a3, b0[sn], b1[sn]);
        }
        __syncthreads();
    }

#pragma unroll
    for (int sn = 0; sn < 4; sn++) {
        const int col = n0 + wn0 + sn * 8 + 2 * tig;
        const float bb0 = bias[col], bb1 = bias[col + 1];
#pragma unroll
        for (int sm = 0; sm < 4; sm++) {
            const int row = m0 + wm0 + sm * 16 + g;
            float2 r0, r1;
            r0.x = acc[sm][sn][0] + bb0; r0.y = acc[sm][sn][1] + bb1;
            r1.x = acc[sm][sn][2] + bb0; r1.y = acc[sm][sn][3] + bb1;
            *(float2*)&C[(size_t)row * N + col]       = r0;
            *(float2*)&C[(size_t)(row + 8) * N + col] = r1;
        }
    }
}

// ---------------------------------------------------------------------------
// Kernel 2: scores = (Q @ K^T) / 8, per (b,h), causal block-skipped. tf32 MMA.
// grid: (k_tile=16, q_tile=16, 24). 128x128 block, K=64.
// ---------------------------------------------------------------------------
__global__ __launch_bounds__(256, 2) void scores_tc()
{
    const int bx = blockIdx.x, by = blockIdx.y;
    if (bx > by) return;                 // above diagonal: never read
    const int bh = blockIdx.z;
    const int b  = bh / Hn, h = bh % Hn;

    const float* Q  = g_qkv + (size_t)b * Ln * D3 + h * DKn;
    const float* Kp = g_qkv + (size_t)b * Ln * D3 + Dn + h * DKn;
    float*       C  = g_scores + (size_t)bh * Ln * Ln;

    __shared__ uint32_t As[8][136];   // [k][q]
    __shared__ uint32_t Bs[8][136];   // [k][kv]

    const int tid  = threadIdx.x;
    const int lane = tid & 31;
    const int wid  = tid >> 5;
    const int g    = lane >> 2;
    const int tig  = lane & 3;
    const int wm0  = (wid >> 2) * 64;
    const int wn0  = (wid & 3) * 32;
    const int m0   = by * 128;
    const int n0   = bx * 128;

    const int row = tid >> 1;             // 0..127
    const int c4  = (tid & 1) * 4;        // 0 or 4

    const float* Qg = Q  + (size_t)(m0 + row) * D3 + c4;
    const float* Kg = Kp + (size_t)(n0 + row) * D3 + c4;

    float acc[4][4][4];
#pragma unroll
    for (int i = 0; i < 4; i++)
#pragma unroll
        for (int j = 0; j < 4; j++)
#pragma unroll
            for (int r = 0; r < 4; r++) acc[i][j][r] = 0.f;

    float4 av = *(const float4*)(Qg);
    float4 bv = *(const float4*)(Kg);

    for (int kt = 0; kt < DKn; kt += 8) {
        As[c4 + 0][row] = f2tf32(av.x);
        As[c4 + 1][row] = f2tf32(av.y);
        As[c4 + 2][row] = f2tf32(av.z);
        As[c4 + 3][row] = f2tf32(av.w);
        Bs[c4 + 0][row] = f2tf32(bv.x);
        Bs[c4 + 1][row] = f2tf32(bv.y);
        Bs[c4 + 2][row] = f2tf32(bv.z);
        Bs[c4 + 3][row] = f2tf32(bv.w);
        __syncthreads();

        if (kt + 8 < DKn) {
            av = *(const float4*)(Qg + kt + 8);
            bv = *(const float4*)(Kg + kt + 8);
        }

        uint32_t b0[4], b1[4];
#pragma unroll
        for (int sn = 0; sn < 4; sn++) {
            b0[sn] = Bs[tig][wn0 + sn * 8 + g];
            b1[sn] = Bs[tig + 4][wn0 + sn * 8 + g];
        }
#pragma unroll
        for (int sm = 0; sm < 4; sm++) {
            const int mb = wm0 + sm * 16;
            uint32_t a0 = As[tig][mb + g];
            uint32_t a1 = As[tig][mb + 8 + g];
            uint32_t a2 = As[tig + 4][mb + g];
            uint32_t a3 = As[tig + 4][mb + 8 + g];
#pragma unroll
            for (int sn = 0; sn < 4; sn++)
                mma8(acc[sm][sn], a0, a1, a2, a3, b0[sn], b1[sn]);
        }
        __syncthreads();
    }

    const float scale = 0.125f;
#pragma unroll
    for (int sn = 0; sn < 4; sn++) {
        const int col = n0 + wn0 + sn * 8 + 2 * tig;
#pragma unroll
        for (int sm = 0; sm < 4; sm++) {
            const int row2 = m0 + wm0 + sm * 16 + g;
            float2 r0, r1;
            r0.x = acc[sm][sn][0] * scale; r0.y = acc[sm][sn][1] * scale;
            r1.x = acc[sm][sn][2] * scale; r1.y = acc[sm][sn][3] * scale;
            *(float2*)&C[(size_t)row2 * Ln + col]       = r0;
            *(float2*)&C[(size_t)(row2 + 8) * Ln + col] = r1;
        }
    }
}

// ---------------------------------------------------------------------------
// Kernel 3: causal softmax over row q (valid length q+1), in place.
// Zero-pads (q, round_up_128(q+1)) so PV reads full 128-tiles.
// ---------------------------------------------------------------------------
__global__ __launch_bounds__(256) void softmax_kernel()
{
    const int q  = blockIdx.x;
    const int bh = blockIdx.y;
    float* row = g_scores + ((size_t)bh * Ln + q) * Ln;
    const int n = q + 1;
    const int tid  = threadIdx.x;
    const int lane = tid & 31;
    const int warp = tid >> 5;

    __shared__ float sred[8];
    __shared__ float sbc;

    float v[8];
    float mx = -3.4e38f;
#pragma unroll
    for (int j = 0; j < 8; j++) {
        int idx = tid + j * 256;
        v[j] = (idx < n) ? row[idx] : -3.4e38f;
        mx = fmaxf(mx, v[j]);
    }
#pragma unroll
    for (int off = 16; off > 0; off >>= 1)
        mx = fmaxf(mx, __shfl_xor_sync(0xFFFFFFFFu, mx, off));
    if (lane == 0) sred[warp] = mx;
    __syncthreads();
    if (tid == 0) {
        float m = sred[0];
#pragma unroll
        for (int w = 1; w < 8; w++) m = fmaxf(m, sred[w]);
        sbc = m;
    }
    __syncthreads();
    mx = sbc;

    float s = 0.f;
#pragma unroll
    for (int j = 0; j < 8; j++) {
        int idx = tid + j * 256;
        if (idx < n) { v[j] = __expf(v[j] - mx); s += v[j]; }
        else          v[j] = 0.f;
    }
#pragma unroll
    for (int off = 16; off > 0; off >>= 1)
        s += __shfl_xor_sync(0xFFFFFFFFu, s, off);
    __syncthreads();
    if (lane == 0) sred[warp] = s;
    __syncthreads();
    if (tid == 0) {
        float t = 0.f;
#pragma unroll
        for (int w = 0; w < 8; w++) t += sred[w];
        sbc = 1.f / t;
    }
    __syncthreads();
    const float inv = sbc;

#pragma unroll
    for (int j = 0; j < 8; j++) {
        int idx = tid + j * 256;
        if (idx < n) row[idx] = v[j] * inv;
    }
    const int pad_end = ((q >> 7) + 1) << 7;
    for (int idx = n + tid; idx < pad_end; idx += 256) row[idx] = 0.f;
}

// ---------------------------------------------------------------------------
// Kernel 4: O = P @ V, per (b,h). tf32 MMA. 128x64 block, 8 warps (4m x 2n),
// each warp 32x32. Heavy-first scheduling: qt = 15 - blockIdx.y.
// ---------------------------------------------------------------------------
__global__ __launch_bounds__(256, 2) void pv_tc()
{
    const int qt = (int)(gridDim.y - 1) - (int)blockIdx.y;  // heavy blocks first
    const int bh = blockIdx.z;
    const int b  = bh / Hn, h = bh % Hn;

    const float* P = g_scores + (size_t)bh * Ln * Ln;
    const float* V = g_qkv + (size_t)b * Ln * D3 + 2 * Dn + h * DKn;
    float*       O = g_y + (size_t)b * Ln * Dn + h * DKn;

    __shared__ uint32_t As[8][136];   // [k][q]
    __shared__ uint32_t Bs[8][72];    // [k][d]  (72 % 32 == 8: conflict-free frags)

    const int tid  = threadIdx.x;
    const int lane = tid & 31;
    const int wid  = tid >> 5;
    const int g    = lane >> 2;
    const int tig  = lane & 3;
    const int wm0  = (wid >> 1) * 32;  // 0..96
    const int wn0  = (wid & 1) * 32;   // 0/32
    const int m0   = qt * 128;

    const int arow = tid >> 1;
    const int ac4  = (tid & 1) * 4;
    const int vrow = tid >> 5;             // 0..7
    const int vc2  = (tid & 31) * 2;       // 0..62

    const float* Ag = P + (size_t)(m0 + arow) * Ln + ac4;
    const float* Vg = V + (size_t)vrow * D3 + vc2;

    float acc[2][4][4];
#pragma unroll
    for (int i = 0; i < 2; i++)
#pragma unroll
        for (int j = 0; j < 4; j++)
#pragma unroll
            for (int r = 0; r < 4; r++) acc[i][j][r] = 0.f;

    const int nkt = (qt + 1) * 128;        // causal bound (zero-padded)

    float4 av = *(const float4*)(Ag);
    float2 vv = *(const float2*)(Vg);

    for (int kt = 0; kt < nkt; kt += 8) {
        As[ac4 + 0][arow] = f2tf32(av.x);
        As[ac4 + 1][arow] = f2tf32(av.y);
        As[ac4 + 2][arow] = f2tf32(av.z);
        As[ac4 + 3][arow] = f2tf32(av.w);
        {
            uint2 p;
            p.x = f2tf32(vv.x); p.y = f2tf32(vv.y);
            *(uint2*)&Bs[vrow][vc2] = p;
        }
        __syncthreads();

        if (kt + 8 < nkt) {
            av = *(const float4*)(Ag + kt + 8);
            vv = *(const float2*)(Vg + (size_t)(kt + 8) * D3);
        }

        uint32_t b0[4], b1[4];
#pragma unroll
        for (int sn = 0; sn < 4; sn++) {
            b0[sn] = Bs[tig][wn0 + sn * 8 + g];
            b1[sn] = Bs[tig + 4][wn0 + sn * 8 + g];
        }
#pragma unroll
        for (int sm = 0; sm < 2; sm++) {
            const int mb = wm0 + sm * 16;
            uint32_t a0 = As[tig][mb + g];
            uint32_t a1 = As[tig][mb + 8 + g];
            uint32_t a2 = As[tig + 4][mb + g];
            uint32_t a3 = As[tig + 4][mb + 8 + g];
#pragma unroll
            for (int sn = 0; sn < 4; sn++)
                mma8(acc[sm][sn], a0, a1, a2, a3, b0[sn], b1[sn]);
        }
        __syncthreads();
    }

#pragma unroll
    for (int sn = 0; sn < 4; sn++) {
        const int col = wn0 + sn * 8 + 2 * tig;
#pragma unroll
        for (int sm = 0; sm < 2; sm++) {
            const int row = m0 + wm0 + sm * 16 + g;
            float2 r0, r1;
            r0.x = acc[sm][sn][0]; r0.y = acc[sm][sn][1];
            r1.x = acc[sm][sn][2]; r1.y = acc[sm][sn][3];
            *(float2*)&O[(size_t)row * Dn + col]       = r0;
            *(float2*)&O[(size_t)(row + 8) * Dn + col] = r1;
        }
    }
}

// ---------------------------------------------------------------------------
// Launch
// ---------------------------------------------------------------------------
extern "C" void kernel_launch(void* const* d_in, const int* in_sizes, int n_in,
                              void* d_out, int out_size)
{
    (void)in_sizes; (void)n_in; (void)out_size;
    const float* x    = (const float*)d_in[0];
    // d_in[1] = additive causal mask — implemented structurally, unused.
    const float* Wqkv = (const float*)d_in[2];
    const float* bqkv = (const float*)d_in[3];
    const float* Wo   = (const float*)d_in[4];
    const float* bo   = (const float*)d_in[5];
    float* out = (float*)d_out;

    float *p_qkv = nullptr, *p_y = nullptr;
    cudaGetSymbolAddress((void**)&p_qkv, g_qkv);
    cudaGetSymbolAddress((void**)&p_y, g_y);

    // 1) QKV projection: (4096 x 768) @ (768 x 2304) + bqkv
    sgemm_bias_tc<<<dim3(D3 / 128, Mrows / 128), 256>>>(
        x, Wqkv, bqkv, p_qkv, Mrows, D3, Dn);

    // 2) Scores: Q K^T / sqrt(dk), causal block-skipped
    scores_tc<<<dim3(Ln / 128, Ln / 128, Bn * Hn), 256>>>();

    // 3) Causal softmax with zero padding
    softmax_kernel<<<dim3(Ln, Bn * Hn), 256>>>();

    // 4) PV: O = P @ V (heavy-first)
    pv_tc<<<dim3(1, Ln / 128, Bn * Hn), 256>>>();

    // 5) Output projection: (4096 x 768) @ (768 x 768) + bo
    sgemm_bias_tc<<<dim3(Dn / 128, Mrows / 128), 256>>>(
        p_y, Wo, bo, out, Mrows, Dn, Dn);
}